// round 2
// baseline (speedup 1.0000x reference)
#include <cuda_runtime.h>

// ---------------------------------------------------------------------------
// SSIM (fused): 5 separable 11-tap Gaussian blurs + SSIM map + global mean.
// Input: img1, img2 fp32 (64,1,512,512). Output: single fp32 scalar (mean).
// ---------------------------------------------------------------------------

#define IMG      512
#define TW       32
#define TH       32
#define HALO     5
#define IN_DIM   42              // TW + 2*HALO
#define SROW     44              // padded row stride (floats) for product arrays
#define HROW     33              // row stride (floats) for horizontal results
#define NCH      5
#define NTHREADS 256

// 1-D Gaussian, sigma=1.5, 11 taps, normalized.
// Expanded as a macro so it can be instantiated as a local const array inside
// device code (fully unrolled loops -> ptxas folds these into FFMA immediates).
#define GW_INIT { 0.00102837f, 0.00759876f, 0.03600077f, 0.10936070f, \
                  0.21300553f, 0.26601173f, 0.21300553f, 0.10936070f, \
                  0.03600077f, 0.00759876f, 0.00102837f }

#define SSIM_C1 0.0001f   // 0.01^2
#define SSIM_C2 0.0009f   // 0.03^2

static __device__ double g_acc;

__global__ void zero_acc_kernel() { g_acc = 0.0; }

__global__ void finalize_kernel(float* out) {
    // total pixels = 64 * 512 * 512 = 16777216
    out[0] = (float)(g_acc * (1.0 / 16777216.0));
}

// Dynamic smem layout:
//   sC[5][IN_DIM][SROW]  : a, b, a*a, b*b, a*b        (with zero padding applied)
//   sH[5][IN_DIM][HROW]  : horizontally blurred rows  (only cols 0..31 used)
#define SC_SIZE (NCH * IN_DIM * SROW)
#define SH_SIZE (NCH * IN_DIM * HROW)
#define SMEM_BYTES ((SC_SIZE + SH_SIZE) * (int)sizeof(float))

__global__ __launch_bounds__(NTHREADS, 2)
void ssim_kernel(const float* __restrict__ img1, const float* __restrict__ img2) {
    extern __shared__ float smem[];
    float* sC = smem;            // [NCH][IN_DIM][SROW]
    float* sH = smem + SC_SIZE;  // [NCH][IN_DIM][HROW]
    __shared__ float red[8];

    const int t  = threadIdx.x;
    const int gx0 = blockIdx.x * TW - HALO;
    const int gy0 = blockIdx.y * TH - HALO;
    const float* base1 = img1 + (size_t)blockIdx.z * (IMG * IMG);
    const float* base2 = img2 + (size_t)blockIdx.z * (IMG * IMG);

    // ---- Phase 1: global load (zero padded) + pointwise products -> smem ----
    // Covers the full padded stride so cols [42,44) are zeroed (safe for float4
    // reads in the horizontal pass).
    for (int idx = t; idx < IN_DIM * SROW; idx += NTHREADS) {
        const int r = idx / SROW;
        const int c = idx - r * SROW;
        const int gy = gy0 + r;
        const int gx = gx0 + c;
        float a = 0.0f, b = 0.0f;
        if (c < IN_DIM && (unsigned)gy < (unsigned)IMG && (unsigned)gx < (unsigned)IMG) {
            const int g = gy * IMG + gx;
            a = base1[g];
            b = base2[g];
        }
        const int o = r * SROW + c;
        sC[0 * IN_DIM * SROW + o] = a;
        sC[1 * IN_DIM * SROW + o] = b;
        sC[2 * IN_DIM * SROW + o] = a * a;
        sC[3 * IN_DIM * SROW + o] = b * b;
        sC[4 * IN_DIM * SROW + o] = a * b;
    }
    __syncthreads();

    // ---- Phase 2: horizontal blur. One thread per (channel,row) strip. ----
    // 5*42 = 210 strips; register sliding window over 42 inputs -> 32 outputs.
    if (t < NCH * IN_DIM) {
        const float gw[11] = GW_INIT;
        const int ch = t / IN_DIM;
        const int r  = t - ch * IN_DIM;
        const float* row = &sC[(ch * IN_DIM + r) * SROW];

        float x[44];
#pragma unroll
        for (int i = 0; i < 11; i++) {
            const float4 v = *reinterpret_cast<const float4*>(row + 4 * i);
            x[4 * i + 0] = v.x;
            x[4 * i + 1] = v.y;
            x[4 * i + 2] = v.z;
            x[4 * i + 3] = v.w;
        }

        float* hrow = &sH[(ch * IN_DIM + r) * HROW];
#pragma unroll
        for (int c = 0; c < TW; c++) {
            float acc = gw[0] * x[c];
#pragma unroll
            for (int k = 1; k < 11; k++) acc = fmaf(gw[k], x[c + k], acc);
            hrow[c] = acc;   // stride-33 rows: bank = (r + c) mod 32, conflict-free
        }
    }
    __syncthreads();

    // ---- Phase 3: vertical blur (4 rows/thread) + SSIM + reduction ----
    {
        const float gw[11] = GW_INIT;
        const int col = t & 31;        // 0..31
        const int rg  = t >> 5;        // 0..7
        const int r0  = rg * 4;

        float res[NCH][4];
#pragma unroll
        for (int ch = 0; ch < NCH; ch++) {
            const float* p = &sH[(ch * IN_DIM + r0) * HROW + col];
            float y[14];
#pragma unroll
            for (int j = 0; j < 14; j++) y[j] = p[j * HROW];
#pragma unroll
            for (int i = 0; i < 4; i++) {
                float acc = gw[0] * y[i];
#pragma unroll
                for (int k = 1; k < 11; k++) acc = fmaf(gw[k], y[i + k], acc);
                res[ch][i] = acc;
            }
        }

        float lsum = 0.0f;
#pragma unroll
        for (int i = 0; i < 4; i++) {
            const float m1  = res[0][i];
            const float m2  = res[1][i];
            const float m1s = m1 * m1;
            const float m2s = m2 * m2;
            const float m12 = m1 * m2;
            const float s1  = res[2][i] - m1s;
            const float s2  = res[3][i] - m2s;
            const float s12 = res[4][i] - m12;
            const float num = (2.0f * m12 + SSIM_C1) * (2.0f * s12 + SSIM_C2);
            const float den = (m1s + m2s + SSIM_C1) * (s1 + s2 + SSIM_C2);
            lsum += num / den;
        }

        // warp reduce
#pragma unroll
        for (int off = 16; off > 0; off >>= 1)
            lsum += __shfl_xor_sync(0xffffffffu, lsum, off);
        if ((t & 31) == 0) red[t >> 5] = lsum;
        __syncthreads();
        if (t == 0) {
            float s = 0.0f;
#pragma unroll
            for (int i = 0; i < 8; i++) s += red[i];
            atomicAdd(&g_acc, (double)s);
        }
    }
}

extern "C" void kernel_launch(void* const* d_in, const int* in_sizes, int n_in,
                              void* d_out, int out_size) {
    const float* img1 = (const float*)d_in[0];
    const float* img2 = (const float*)d_in[1];
    float* out = (float*)d_out;

    cudaFuncSetAttribute(ssim_kernel,
                         cudaFuncAttributeMaxDynamicSharedMemorySize, SMEM_BYTES);

    zero_acc_kernel<<<1, 1>>>();
    dim3 grid(IMG / TW, IMG / TH, 64);   // 16 x 16 x 64 = 16384 blocks
    ssim_kernel<<<grid, NTHREADS, SMEM_BYTES>>>(img1, img2);
    finalize_kernel<<<1, 1>>>(out);
}

// round 3
// speedup vs baseline: 1.0392x; 1.0392x over previous
#include <cuda_runtime.h>

// ---------------------------------------------------------------------------
// SSIM (fused): 5 separable 11-tap Gaussian blurs + SSIM map + global mean.
// Input: img1, img2 fp32 (64,1,512,512). Output: single fp32 scalar (mean).
//
// Tile: 32 cols x 64 rows output per block. Phases:
//   1) global load (zero-padded) + pointwise products -> smem (5 planes)
//   2) horizontal 11-tap blur, IN-PLACE per row (thread owns whole row)
//   3) vertical 11-tap blur + SSIM formula + block/global reduction
// All conv taps are literal constants -> FFMA-with-immediate (rt_SMSP=1).
// ---------------------------------------------------------------------------

#define IMG      512
#define TW       32
#define TH       64
#define HALO     5
#define ROWS     74              // TH + 2*HALO
#define SROW     44              // padded row stride (floats); cols 42,43 unused pads
#define NCH      5
#define NTHREADS 256
#define PLANE    (ROWS * SROW)   // 3256 floats per channel plane

#define SSIM_C1 0.0001f   // 0.01^2
#define SSIM_C2 0.0009f   // 0.03^2

// 1-D Gaussian, sigma=1.5, 11 taps, normalized — as literals so every tap is
// an FFMA with immediate multiplier.
#define GW0 1.0283735e-03f
#define GW1 7.5987582e-03f
#define GW2 3.6000773e-02f
#define GW3 1.0936068e-01f
#define GW4 2.1300554e-01f
#define GW5 2.6601174e-01f

#define CONV11(X, c)                                                      \
    fmaf(GW0, (X)[(c)+0], fmaf(GW1, (X)[(c)+1], fmaf(GW2, (X)[(c)+2],     \
    fmaf(GW3, (X)[(c)+3], fmaf(GW4, (X)[(c)+4], fmaf(GW5, (X)[(c)+5],     \
    fmaf(GW4, (X)[(c)+6], fmaf(GW3, (X)[(c)+7], fmaf(GW2, (X)[(c)+8],     \
    fmaf(GW1, (X)[(c)+9], GW0 * (X)[(c)+10]))))))))))

static __device__ double g_acc;

__global__ void zero_acc_kernel() { g_acc = 0.0; }

__global__ void finalize_kernel(float* out) {
    out[0] = (float)(g_acc * (1.0 / 16777216.0));  // 64*512*512 pixels
}

#define SMEM_BYTES (NCH * PLANE * (int)sizeof(float))   // 65,120 B

__global__ __launch_bounds__(NTHREADS, 2)
void ssim_kernel(const float* __restrict__ img1, const float* __restrict__ img2) {
    extern __shared__ float sC[];   // [NCH][ROWS][SROW]
    __shared__ float red[8];

    const int t    = threadIdx.x;
    const int lane = t & 31;
    const int wid  = t >> 5;
    const int gx0  = blockIdx.x * TW - HALO;
    const int gy0  = blockIdx.y * TH - HALO;
    const float* base1 = img1 + (size_t)blockIdx.z * (IMG * IMG);
    const float* base2 = img2 + (size_t)blockIdx.z * (IMG * IMG);

    // ---- Phase 1: load (zero-padded) + products. Warp per row, coalesced. ----
    // Each lane covers col=lane and (lane<10) col=lane+32; cols 0..41 written.
    for (int r = wid; r < ROWS; r += 8) {
        const int gy = gy0 + r;
        const bool yok = (unsigned)gy < (unsigned)IMG;
        const float* r1 = base1 + gy * IMG;
        const float* r2 = base2 + gy * IMG;
        const int o = r * SROW;

        {
            const int c  = lane;
            const int gx = gx0 + c;
            const bool ok = yok && (unsigned)gx < (unsigned)IMG;
            const float a = ok ? r1[gx] : 0.0f;
            const float b = ok ? r2[gx] : 0.0f;
            sC[0 * PLANE + o + c] = a;
            sC[1 * PLANE + o + c] = b;
            sC[2 * PLANE + o + c] = a * a;
            sC[3 * PLANE + o + c] = b * b;
            sC[4 * PLANE + o + c] = a * b;
        }
        if (lane < 10) {
            const int c  = lane + 32;
            const int gx = gx0 + c;
            const bool ok = yok && (unsigned)gx < (unsigned)IMG;
            const float a = ok ? r1[gx] : 0.0f;
            const float b = ok ? r2[gx] : 0.0f;
            sC[0 * PLANE + o + c] = a;
            sC[1 * PLANE + o + c] = b;
            sC[2 * PLANE + o + c] = a * a;
            sC[3 * PLANE + o + c] = b * b;
            sC[4 * PLANE + o + c] = a * b;
        }
    }
    __syncthreads();

    // ---- Phase 2: horizontal blur, IN-PLACE. One thread per (ch,row) strip. ----
    // Preload all 44 floats of the row into registers (11x float4), then
    // overwrite cols 0..31 of the same row. x[42],x[43] are pad (never used).
    for (int u = t; u < NCH * ROWS; u += NTHREADS) {
        const int ch = u / ROWS;
        const int r  = u - ch * ROWS;
        float* row = &sC[ch * PLANE + r * SROW];

        float x[44];
#pragma unroll
        for (int i = 0; i < 11; i++) {
            const float4 v = *reinterpret_cast<const float4*>(row + 4 * i);
            x[4 * i + 0] = v.x;
            x[4 * i + 1] = v.y;
            x[4 * i + 2] = v.z;
            x[4 * i + 3] = v.w;
        }
#pragma unroll
        for (int c = 0; c < TW; c++) {
            row[c] = CONV11(x, c);
        }
    }
    __syncthreads();

    // ---- Phase 3: vertical blur (8 rows/thread) + SSIM + reduction ----
    {
        const int col = lane;          // 0..31
        const int r0  = wid * 8;       // 0,8,...,56

        float res[NCH][8];
#pragma unroll
        for (int ch = 0; ch < NCH; ch++) {
            const float* p = &sC[ch * PLANE + r0 * SROW + col];
            float y[18];
#pragma unroll
            for (int j = 0; j < 18; j++) y[j] = p[j * SROW];
#pragma unroll
            for (int i = 0; i < 8; i++) res[ch][i] = CONV11(y, i);
        }

        float lsum = 0.0f;
#pragma unroll
        for (int i = 0; i < 8; i++) {
            const float m1  = res[0][i];
            const float m2  = res[1][i];
            const float m1s = m1 * m1;
            const float m2s = m2 * m2;
            const float m12 = m1 * m2;
            const float s1  = res[2][i] - m1s;
            const float s2  = res[3][i] - m2s;
            const float s12 = res[4][i] - m12;
            const float num = (2.0f * m12 + SSIM_C1) * (2.0f * s12 + SSIM_C2);
            const float den = (m1s + m2s + SSIM_C1) * (s1 + s2 + SSIM_C2);
            lsum += __fdividef(num, den);
        }

        // warp reduce, then block reduce, then one atomic per block
#pragma unroll
        for (int off = 16; off > 0; off >>= 1)
            lsum += __shfl_xor_sync(0xffffffffu, lsum, off);
        if (lane == 0) red[wid] = lsum;
        __syncthreads();
        if (t == 0) {
            float s = 0.0f;
#pragma unroll
            for (int i = 0; i < 8; i++) s += red[i];
            atomicAdd(&g_acc, (double)s);
        }
    }
}

extern "C" void kernel_launch(void* const* d_in, const int* in_sizes, int n_in,
                              void* d_out, int out_size) {
    const float* img1 = (const float*)d_in[0];
    const float* img2 = (const float*)d_in[1];
    float* out = (float*)d_out;

    cudaFuncSetAttribute(ssim_kernel,
                         cudaFuncAttributeMaxDynamicSharedMemorySize, SMEM_BYTES);

    zero_acc_kernel<<<1, 1>>>();
    dim3 grid(IMG / TW, IMG / TH, 64);   // 16 x 8 x 64 = 8192 blocks
    ssim_kernel<<<grid, NTHREADS, SMEM_BYTES>>>(img1, img2);
    finalize_kernel<<<1, 1>>>(out);
}